// round 1
// baseline (speedup 1.0000x reference)
#include <cuda_runtime.h>
#include <cuda_bf16.h>

// Problem constants (fixed shapes for this problem)
#define NN 40000
#define DD 128
#define EE 640000

// Scratch (device globals; no allocation allowed)
__device__ float g_y[NN * DD];        // relu(x @ W^T + b) per node, 20.5 MB (L2-resident)
__device__ int   g_deg[NN];
__device__ int   g_off[NN];
__device__ int   g_cur[NN];
__device__ int   g_csr[EE];

// ---------------------------------------------------------------------------
// Kernel 1: zero degree counters
// ---------------------------------------------------------------------------
__global__ void k_zero_deg(int n) {
    int i = blockIdx.x * blockDim.x + threadIdx.x;
    if (i < n) g_deg[i] = 0;
}

// ---------------------------------------------------------------------------
// Kernel 2: y = relu(x @ W^T + b)  (N x D) @ (D x D)
// Block: 256 threads, computes 64 rows x 128 cols. k-chunked smem tiling.
// ---------------------------------------------------------------------------
__global__ __launch_bounds__(256) void k_gemm_relu(
    const float* __restrict__ x, const float* __restrict__ W,
    const float* __restrict__ b, int nrows)
{
    __shared__ float xs[64][32];     // x tile  (writes: lane=kk -> conflict-free)
    __shared__ float wt[32][132];    // W^T tile, padded stride 132 (16B-aligned rows)

    const int t    = threadIdx.x;
    const int row0 = blockIdx.x * 64;
    const int ty   = t >> 5;         // 0..7  -> 8 rows each
    const int tx   = t & 31;         // 0..31 -> 4 cols each

    float acc[8][4];
#pragma unroll
    for (int r = 0; r < 8; r++)
#pragma unroll
        for (int c = 0; c < 4; c++) acc[r][c] = 0.f;

    for (int kc = 0; kc < DD; kc += 32) {
        // load x tile: 64x32
#pragma unroll
        for (int i = t; i < 64 * 32; i += 256) {
            int r = i >> 5, kk = i & 31;
            int row = row0 + r;
            xs[r][kk] = (row < nrows) ? x[row * DD + kc + kk] : 0.f;
        }
        // load W tile transposed: wt[kk][c] = W[c][kc+kk] (coalesced gmem reads)
#pragma unroll
        for (int i = t; i < 128 * 32; i += 256) {
            int c = i >> 5, kk = i & 31;
            wt[kk][c] = W[c * DD + kc + kk];
        }
        __syncthreads();

#pragma unroll
        for (int kk = 0; kk < 32; kk++) {
            float4 wv = *(const float4*)&wt[kk][tx * 4];  // conflict-free LDS.128
            float xv[8];
#pragma unroll
            for (int r = 0; r < 8; r++) xv[r] = xs[ty * 8 + r][kk];  // broadcast
#pragma unroll
            for (int r = 0; r < 8; r++) {
                acc[r][0] = fmaf(xv[r], wv.x, acc[r][0]);
                acc[r][1] = fmaf(xv[r], wv.y, acc[r][1]);
                acc[r][2] = fmaf(xv[r], wv.z, acc[r][2]);
                acc[r][3] = fmaf(xv[r], wv.w, acc[r][3]);
            }
        }
        __syncthreads();
    }

    float4 bv = *(const float4*)&b[tx * 4];
#pragma unroll
    for (int r = 0; r < 8; r++) {
        int row = row0 + ty * 8 + r;
        if (row < nrows) {
            float4 o;
            o.x = fmaxf(acc[r][0] + bv.x, 0.f);
            o.y = fmaxf(acc[r][1] + bv.y, 0.f);
            o.z = fmaxf(acc[r][2] + bv.z, 0.f);
            o.w = fmaxf(acc[r][3] + bv.w, 0.f);
            *(float4*)&g_y[row * DD + tx * 4] = o;
        }
    }
}

// ---------------------------------------------------------------------------
// Kernel 3: histogram of dst degrees
// ---------------------------------------------------------------------------
__global__ void k_hist(const int* __restrict__ e, int ne) {
    int i = blockIdx.x * blockDim.x + threadIdx.x;
    if (i < ne) atomicAdd(&g_deg[e[2 * i + 1]], 1);
}

// ---------------------------------------------------------------------------
// Kernel 4: exclusive prefix scan over deg -> off, cur  (single block, 1024 thr)
// ---------------------------------------------------------------------------
__global__ __launch_bounds__(1024) void k_scan(int n) {
    __shared__ int warpsum[32];
    __shared__ int carry;
    const int t = threadIdx.x;
    const int lane = t & 31, wid = t >> 5;
    if (t == 0) carry = 0;
    __syncthreads();

    const int nRound = ((n + 1023) / 1024) * 1024;
    for (int base = 0; base < nRound; base += 1024) {
        int i = base + t;
        int v = (i < n) ? g_deg[i] : 0;
        // warp inclusive scan
        int s = v;
#pragma unroll
        for (int d = 1; d < 32; d <<= 1) {
            int m = __shfl_up_sync(0xFFFFFFFFu, s, d);
            if (lane >= d) s += m;
        }
        if (lane == 31) warpsum[wid] = s;
        __syncthreads();
        if (t < 32) {
            int ws = warpsum[t];
            int ss = ws;
#pragma unroll
            for (int d = 1; d < 32; d <<= 1) {
                int m = __shfl_up_sync(0xFFFFFFFFu, ss, d);
                if (t >= d) ss += m;
            }
            warpsum[t] = ss - ws;  // exclusive warp offsets
        }
        __syncthreads();
        int excl = s - v + warpsum[wid] + carry;
        if (i < n) { g_off[i] = excl; g_cur[i] = excl; }
        __syncthreads();
        if (t == 1023) carry = excl + v;
        __syncthreads();
    }
}

// ---------------------------------------------------------------------------
// Kernel 5: scatter edges into dst-CSR
// ---------------------------------------------------------------------------
__global__ void k_scatter(const int* __restrict__ e, int ne) {
    int i = blockIdx.x * blockDim.x + threadIdx.x;
    if (i < ne) {
        int d = e[2 * i + 1];
        int p = atomicAdd(&g_cur[d], 1);
        g_csr[p] = e[2 * i];  // src
    }
}

// ---------------------------------------------------------------------------
// Kernel 6: per-dst gather-max over y + residual + RMSNorm.  One warp / node.
// ---------------------------------------------------------------------------
__global__ __launch_bounds__(256) void k_aggregate(
    const float* __restrict__ x, const float* __restrict__ g,
    const float* __restrict__ rb, float* __restrict__ out, int n)
{
    const int node = (blockIdx.x * blockDim.x + threadIdx.x) >> 5;
    const int lane = threadIdx.x & 31;
    if (node >= n) return;

    const int start = g_off[node];
    const int cnt   = g_deg[node];
    const float4* yv = (const float4*)g_y;

    float4 agg = make_float4(0.f, 0.f, 0.f, 0.f);
    int j = 0;
    // unrolled-by-4 for memory-level parallelism
    for (; j + 4 <= cnt; j += 4) {
        int s0 = g_csr[start + j];
        int s1 = g_csr[start + j + 1];
        int s2 = g_csr[start + j + 2];
        int s3 = g_csr[start + j + 3];
        float4 v0 = yv[s0 * 32 + lane];
        float4 v1 = yv[s1 * 32 + lane];
        float4 v2 = yv[s2 * 32 + lane];
        float4 v3 = yv[s3 * 32 + lane];
        agg.x = fmaxf(agg.x, fmaxf(fmaxf(v0.x, v1.x), fmaxf(v2.x, v3.x)));
        agg.y = fmaxf(agg.y, fmaxf(fmaxf(v0.y, v1.y), fmaxf(v2.y, v3.y)));
        agg.z = fmaxf(agg.z, fmaxf(fmaxf(v0.z, v1.z), fmaxf(v2.z, v3.z)));
        agg.w = fmaxf(agg.w, fmaxf(fmaxf(v0.w, v1.w), fmaxf(v2.w, v3.w)));
    }
    for (; j < cnt; j++) {
        int s = g_csr[start + j];
        float4 v = yv[s * 32 + lane];
        agg.x = fmaxf(agg.x, v.x);
        agg.y = fmaxf(agg.y, v.y);
        agg.z = fmaxf(agg.z, v.z);
        agg.w = fmaxf(agg.w, v.w);
    }

    float4 xv = ((const float4*)x)[node * 32 + lane];
    float4 h;
    h.x = xv.x + agg.x; h.y = xv.y + agg.y;
    h.z = xv.z + agg.z; h.w = xv.w + agg.w;

    float ss = h.x * h.x + h.y * h.y + h.z * h.z + h.w * h.w;
#pragma unroll
    for (int d = 16; d; d >>= 1) ss += __shfl_xor_sync(0xFFFFFFFFu, ss, d);

    float inv = rsqrtf(ss * (1.0f / DD) + 1e-5f);

    float4 gv = ((const float4*)g)[lane];
    float4 rv = ((const float4*)rb)[lane];
    float4 o;
    o.x = h.x * inv * gv.x + rv.x;
    o.y = h.y * inv * gv.y + rv.y;
    o.z = h.z * inv * gv.z + rv.z;
    o.w = h.w * inv * gv.w + rv.w;
    ((float4*)out)[node * 32 + lane] = o;
}

// ---------------------------------------------------------------------------
// Launch
// ---------------------------------------------------------------------------
extern "C" void kernel_launch(void* const* d_in, const int* in_sizes, int n_in,
                              void* d_out, int out_size)
{
    const float* x  = (const float*)d_in[0];
    const int*   e  = (const int*)  d_in[1];
    const float* W  = (const float*)d_in[2];
    const float* b  = (const float*)d_in[3];
    const float* g  = (const float*)d_in[4];
    const float* rb = (const float*)d_in[5];
    float* out = (float*)d_out;

    const int n  = in_sizes[0] / DD;   // 40000
    const int ne = in_sizes[1] / 2;    // 640000

    k_zero_deg<<<(n + 255) / 256, 256>>>(n);
    k_gemm_relu<<<(n + 63) / 64, 256>>>(x, W, b, n);
    k_hist<<<(ne + 255) / 256, 256>>>(e, ne);
    k_scan<<<1, 1024>>>(n);
    k_scatter<<<(ne + 255) / 256, 256>>>(e, ne);
    k_aggregate<<<(n * 32 + 255) / 256, 256>>>(x, g, rb, out, n);
}